// round 7
// baseline (speedup 1.0000x reference)
#include <cuda_runtime.h>
#include <cuda_bf16.h>
#include <cstdint>

#define SL 256        // syndrome bit length (fixed for this problem family)
#define MAX_T 4096    // scratch capacity for table entries (problem uses 2048)
#define NB 8192       // hash-table slots (power of 2, load factor <= 0.5)

// Scratch in __device__ globals (no allocation allowed).
// g_table: 0 = empty, else entry_index + 1. Zero-init == all-empty.
// Insertion is idempotent across graph replays.
__device__ uint64_t     g_pk[MAX_T * 4];
__device__ unsigned int g_table[NB];
// Grid-barrier state. Reset to 0 by the last-exiting block each run.
__device__ unsigned int g_done;
__device__ unsigned int g_exit;

__device__ __forceinline__ uint64_t mix64(uint64_t x) {
    x ^= x >> 30; x *= 0xBF58476D1CE4E5B9ull;
    x ^= x >> 27; x *= 0x94D049BB133111EBull;
    x ^= x >> 31;
    return x;
}

__device__ __forceinline__ uint64_t fold_hash(uint64_t k0, uint64_t k1,
                                              uint64_t k2, uint64_t k3) {
    return k0 ^ (k1 * 0x9E3779B97F4A7C15ull)
              ^ (k2 * 0xC2B2AE3D27D4EB4Full)
              ^ (k3 * 0x165667B19E3779F9ull);
}

// ---------------------------------------------------------------------------
// Fused kernel: phase 1 builds the hash table (first T global warps, one row
// each), a software grid barrier (safe: all blocks co-resident, see launch),
// then phase 2 does the warp-parallel hash lookup. One launch total.
// ---------------------------------------------------------------------------
__global__ __launch_bounds__(256, 8) void fused_kernel(
    const float* __restrict__ syn,
    const float* __restrict__ tk,
    const float* __restrict__ tv,
    float* __restrict__ out,
    int B, int T)
{
    const int lane = threadIdx.x & 31;
    const int wid  = threadIdx.x >> 5;          // 0..7
    const int gwarp = blockIdx.x * 8 + wid;

    // ---------------- Phase 1: build (first T warps) ----------------
    if (gwarp < T) {
        const float* row = tk + (size_t)gwarp * SL;
        uint32_t w[8];
#pragma unroll
        for (int i = 0; i < 8; i++) {
            float v = row[i * 32 + lane];                 // coalesced 128B
            w[i] = __ballot_sync(0xffffffffu, v > 0.5f);  // warp-uniform
        }
        uint64_t k0 = (uint64_t)w[0] | ((uint64_t)w[1] << 32);
        uint64_t k1 = (uint64_t)w[2] | ((uint64_t)w[3] << 32);
        uint64_t k2 = (uint64_t)w[4] | ((uint64_t)w[5] << 32);
        uint64_t k3 = (uint64_t)w[6] | ((uint64_t)w[7] << 32);

        if (lane == 0)
            *(ulonglong2*)&g_pk[(size_t)gwarp * 4]     = make_ulonglong2(k0, k1);
        if (lane == 1)
            *(ulonglong2*)&g_pk[(size_t)gwarp * 4 + 2] = make_ulonglong2(k2, k3);

        if (lane == 0) {
            uint64_t h = fold_hash(k0, k1, k2, k3);
            unsigned b = (unsigned)mix64(h) & (NB - 1);
            unsigned tag = (unsigned)gwarp + 1u;
            for (;;) {
                unsigned prev = atomicCAS(&g_table[b], 0u, tag);
                if (prev == 0u || prev == tag) break;     // idempotent on replay
                b = (b + 1) & (NB - 1);
            }
        }
    }

    // ---------------- Grid barrier ----------------
    // Safe: grid = 1024 blocks, launch_bounds (256,8) -> 8 blocks/SM x 148
    // SMs = 1184 resident capacity >= 1024, so every block is running and
    // will arrive. Release: threadfence before arrive; acquire: fence after.
    __syncthreads();
    if (threadIdx.x == 0) {
        __threadfence();
        atomicAdd(&g_done, 1u);
        volatile unsigned* done = &g_done;
        while (*done < gridDim.x) { /* spin; L2-resident poll */ }
    }
    __syncthreads();
    __threadfence();

    // ---------------- Phase 2: lookup (one warp per query) ----------------
    int q = blockIdx.x * 8 + wid;
    if (q < B) {
        const float* row = syn + (size_t)q * SL;
        uint32_t w[8];
#pragma unroll
        for (int i = 0; i < 8; i++) {
            float v = row[i * 32 + lane];                 // coalesced 128B
            w[i] = __ballot_sync(0xffffffffu, v > 0.5f);
        }
        uint64_t q0 = (uint64_t)w[0] | ((uint64_t)w[1] << 32);
        uint64_t q1 = (uint64_t)w[2] | ((uint64_t)w[3] << 32);
        uint64_t q2 = (uint64_t)w[4] | ((uint64_t)w[5] << 32);
        uint64_t q3 = (uint64_t)w[6] | ((uint64_t)w[7] << 32);

        uint64_t h = fold_hash(q0, q1, q2, q3);
        unsigned b0 = (unsigned)mix64(h) & (NB - 1);

        int best = 0x7fffffff;
        for (;;) {
            // One coalesced 128B read covers 32 slots of the cluster.
            unsigned slot = (b0 + lane) & (NB - 1);
            unsigned v = g_table[slot];

            unsigned empty_mask = __ballot_sync(0xffffffffu, v == 0u);
            int first_empty = empty_mask ? (__ffs(empty_mask) - 1) : 32;

            // Candidate lanes verify their entry's full 256-bit key in parallel.
            if (v != 0u && lane < first_empty) {
                int idx = (int)v - 1;
                const uint64_t* pk = &g_pk[(size_t)idx * 4];
                ulonglong2 a = *(const ulonglong2*)pk;
                ulonglong2 c = *(const ulonglong2*)(pk + 2);
                if (a.x == q0 && a.y == q1 && c.x == q2 && c.y == q3)
                    best = min(best, idx);                // first match = min idx
            }
            if (first_empty < 32) break;                  // cluster ends here
            b0 = (b0 + 32) & (NB - 1);                    // essentially never
        }
#pragma unroll
        for (int off = 16; off; off >>= 1)
            best = min(best, __shfl_xor_sync(0xffffffffu, best, off));

        // Vectorized emit: 256 floats = 64 float4; 2 per lane.
        float4* orow4 = (float4*)(out + (size_t)q * SL);
        if (best != 0x7fffffff) {
            const float4* vrow4 = (const float4*)(tv + (size_t)best * SL);
            float4 a = vrow4[lane];
            float4 c = vrow4[lane + 32];
            orow4[lane]      = a;
            orow4[lane + 32] = c;
        } else {
            float4 z = make_float4(0.f, 0.f, 0.f, 0.f);
            orow4[lane]      = z;
            orow4[lane + 32] = z;
        }
    }

    // ---------------- Replay-safe reset ----------------
    // The LAST block to exit (all blocks have passed the barrier by then,
    // since each increments g_exit only after its own barrier pass) resets
    // the barrier counters for the next graph replay.
    __syncthreads();
    if (threadIdx.x == 0) {
        unsigned old = atomicAdd(&g_exit, 1u);
        if (old == gridDim.x - 1u) {
            g_done = 0u;
            g_exit = 0u;
            __threadfence();
        }
    }
}

// ---------------------------------------------------------------------------
extern "C" void kernel_launch(void* const* d_in, const int* in_sizes, int n_in,
                              void* d_out, int out_size) {
    const float* syn = (const float*)d_in[0];   // [B, 256]
    const float* tk  = (const float*)d_in[1];   // [T, 256]
    const float* tv  = (const float*)d_in[2];   // [T, 256]
    float* out = (float*)d_out;                 // [B, 256]

    int B = in_sizes[0] / SL;
    int T = in_sizes[1] / SL;

    // 8 warps/block: one query per warp; first T warps also build the table.
    int blocks = (B + 7) / 8;                   // 1024 for B=8192
    fused_kernel<<<blocks, 256>>>(syn, tk, tv, out, B, T);
}

// round 8
// speedup vs baseline: 1.1404x; 1.1404x over previous
#include <cuda_runtime.h>
#include <cuda_bf16.h>
#include <cstdint>

#define SL 256        // syndrome bit length (fixed for this problem family)
#define MAX_T 4096    // scratch capacity for table entries (problem uses 2048)
#define NB 8192       // hash-table slots (power of 2, load factor <= 0.5)

// Scratch in __device__ globals (no allocation allowed).
// g_sidx[slot]: 0 = empty, else entry_index + 1. Zero-init == all-empty.
// g_skey[slot]: full 256-bit key for the entry in that slot (valid iff sidx!=0).
// Insertion is idempotent across graph replays.
__device__ unsigned int g_sidx[NB];
__device__ ulonglong4   g_skey[NB];

__device__ __forceinline__ uint64_t mix64(uint64_t x) {
    x ^= x >> 30; x *= 0xBF58476D1CE4E5B9ull;
    x ^= x >> 27; x *= 0x94D049BB133111EBull;
    x ^= x >> 31;
    return x;
}

__device__ __forceinline__ uint64_t fold_hash(uint64_t k0, uint64_t k1,
                                              uint64_t k2, uint64_t k3) {
    return k0 ^ (k1 * 0x9E3779B97F4A7C15ull)
              ^ (k2 * 0xC2B2AE3D27D4EB4Full)
              ^ (k3 * 0x165667B19E3779F9ull);
}

// ---------------------------------------------------------------------------
// Kernel 1: pack table keys, insert idx+1 + the packed key into the slot.
// One warp per row.
// ---------------------------------------------------------------------------
__global__ __launch_bounds__(256) void build_table_kernel(
    const float* __restrict__ tk, int T)
{
    int row_i = (blockIdx.x * blockDim.x + threadIdx.x) >> 5;
    int lane  = threadIdx.x & 31;
    if (row_i >= T) return;

    const float* row = tk + (size_t)row_i * SL;
    uint32_t w[8];
#pragma unroll
    for (int i = 0; i < 8; i++) {
        float v = row[i * 32 + lane];                   // coalesced 128B
        w[i] = __ballot_sync(0xffffffffu, v > 0.5f);    // warp-uniform
    }
    uint64_t k0 = (uint64_t)w[0] | ((uint64_t)w[1] << 32);
    uint64_t k1 = (uint64_t)w[2] | ((uint64_t)w[3] << 32);
    uint64_t k2 = (uint64_t)w[4] | ((uint64_t)w[5] << 32);
    uint64_t k3 = (uint64_t)w[6] | ((uint64_t)w[7] << 32);

    if (lane == 0) {
        uint64_t h = fold_hash(k0, k1, k2, k3);
        unsigned b = (unsigned)mix64(h) & (NB - 1);
        unsigned tag = (unsigned)row_i + 1u;
        for (;;) {
            unsigned prev = atomicCAS(&g_sidx[b], 0u, tag);
            if (prev == 0u || prev == tag) break;       // idempotent on replay
            b = (b + 1) & (NB - 1);
        }
        // Write the key into the slot (same value on replay; idempotent).
        ulonglong2* kp = (ulonglong2*)&g_skey[b];
        kp[0] = make_ulonglong2(k0, k1);
        kp[1] = make_ulonglong2(k2, k3);
    }
}

// Rare continuation: cluster longer than 32 slots (essentially never at 25% load).
__device__ __noinline__ int probe_more(unsigned b, int lane,
    uint64_t q0, uint64_t q1, uint64_t q2, uint64_t q3)
{
    int best = 0x7fffffff;
    for (;;) {
        unsigned slot = (b + lane) & (NB - 1);
        unsigned s = __ldg(&g_sidx[slot]);
        unsigned empty = __ballot_sync(0xffffffffu, s == 0u);
        int fe = empty ? (__ffs(empty) - 1) : 32;
        if (s != 0u && lane < fe) {
            const ulonglong2* kp = (const ulonglong2*)&g_skey[slot];
            ulonglong2 a = __ldg(kp);
            ulonglong2 c = __ldg(kp + 1);
            if (a.x == q0 && a.y == q1 && c.x == q2 && c.y == q3)
                best = min(best, (int)s - 1);
        }
        if (fe < 32) break;
        b = (b + 32) & (NB - 1);
    }
    return best;
}

// ---------------------------------------------------------------------------
// Kernel 2: one warp handles TWO queries, fully interleaved so both memory
// chains (syndrome -> probe(idx+key in parallel) -> value) are in flight at
// once. Keys live slot-indexed, so probe+verify is a single memory hop.
// ---------------------------------------------------------------------------
__global__ __launch_bounds__(256) void lookup_kernel(
    const float* __restrict__ syn,
    const float* __restrict__ tv,
    float* __restrict__ out,
    int B)
{
    const int lane = threadIdx.x & 31;
    const int gw = blockIdx.x * (blockDim.x >> 5) + (threadIdx.x >> 5);
    const int qa = gw * 2;
    const int qb = qa + 1;
    if (qa >= B) return;
    const bool has_b = (qb < B);

    // ---- Pack both queries (interleaved loads -> 16-wide MLP) ----
    const float* rowa = syn + (size_t)qa * SL;
    const float* rowb = syn + (size_t)(has_b ? qb : qa) * SL;
    uint32_t wa[8], wb[8];
#pragma unroll
    for (int i = 0; i < 8; i++) {
        float va = rowa[i * 32 + lane];
        float vb = rowb[i * 32 + lane];
        wa[i] = __ballot_sync(0xffffffffu, va > 0.5f);
        wb[i] = __ballot_sync(0xffffffffu, vb > 0.5f);
    }
    uint64_t a0 = (uint64_t)wa[0] | ((uint64_t)wa[1] << 32);
    uint64_t a1 = (uint64_t)wa[2] | ((uint64_t)wa[3] << 32);
    uint64_t a2 = (uint64_t)wa[4] | ((uint64_t)wa[5] << 32);
    uint64_t a3 = (uint64_t)wa[6] | ((uint64_t)wa[7] << 32);
    uint64_t b0k = (uint64_t)wb[0] | ((uint64_t)wb[1] << 32);
    uint64_t b1k = (uint64_t)wb[2] | ((uint64_t)wb[3] << 32);
    uint64_t b2k = (uint64_t)wb[4] | ((uint64_t)wb[5] << 32);
    uint64_t b3k = (uint64_t)wb[6] | ((uint64_t)wb[7] << 32);

    unsigned ba = (unsigned)mix64(fold_hash(a0, a1, a2, a3)) & (NB - 1);
    unsigned bb = (unsigned)mix64(fold_hash(b0k, b1k, b2k, b3k)) & (NB - 1);

    // ---- Probe both clusters: idx load + speculative key load in parallel ----
    unsigned slota = (ba + lane) & (NB - 1);
    unsigned slotb = (bb + lane) & (NB - 1);
    unsigned sa = __ldg(&g_sidx[slota]);
    unsigned sb = __ldg(&g_sidx[slotb]);

    ulonglong2 ka0, ka1, kb0, kb1;
    bool spec = (lane < 8);  // cluster length > 8 is vanishingly rare
    if (spec) {
        const ulonglong2* pa = (const ulonglong2*)&g_skey[slota];
        const ulonglong2* pb = (const ulonglong2*)&g_skey[slotb];
        ka0 = __ldg(pa); ka1 = __ldg(pa + 1);
        kb0 = __ldg(pb); kb1 = __ldg(pb + 1);
    }

    unsigned ea = __ballot_sync(0xffffffffu, sa == 0u);
    unsigned eb = __ballot_sync(0xffffffffu, sb == 0u);
    int fea = ea ? (__ffs(ea) - 1) : 32;
    int feb = eb ? (__ffs(eb) - 1) : 32;

    int besta = 0x7fffffff, bestb = 0x7fffffff;
    if (sa != 0u && lane < fea) {
        if (!spec) {  // rare dependent fallback
            const ulonglong2* pa = (const ulonglong2*)&g_skey[slota];
            ka0 = __ldg(pa); ka1 = __ldg(pa + 1);
        }
        if (ka0.x == a0 && ka0.y == a1 && ka1.x == a2 && ka1.y == a3)
            besta = (int)sa - 1;
    }
    if (sb != 0u && lane < feb) {
        if (!spec) {
            const ulonglong2* pb = (const ulonglong2*)&g_skey[slotb];
            kb0 = __ldg(pb); kb1 = __ldg(pb + 1);
        }
        if (kb0.x == b0k && kb0.y == b1k && kb1.x == b2k && kb1.y == b3k)
            bestb = (int)sb - 1;
    }
    if (fea == 32) besta = min(besta, probe_more((ba + 32) & (NB - 1), lane, a0, a1, a2, a3));
    if (feb == 32) bestb = min(bestb, probe_more((bb + 32) & (NB - 1), lane, b0k, b1k, b2k, b3k));

    besta = __reduce_min_sync(0xffffffffu, (unsigned)besta);
    bestb = __reduce_min_sync(0xffffffffu, (unsigned)bestb);

    // ---- Emit both rows (value loads interleaved; float4 vectorized) ----
    float4 va0 = make_float4(0.f, 0.f, 0.f, 0.f), va1 = va0;
    float4 vb0 = va0, vb1 = va0;
    if (besta != 0x7fffffff) {
        const float4* vr = (const float4*)(tv + (size_t)besta * SL);
        va0 = __ldg(vr + lane); va1 = __ldg(vr + lane + 32);
    }
    if (has_b && bestb != 0x7fffffff) {
        const float4* vr = (const float4*)(tv + (size_t)bestb * SL);
        vb0 = __ldg(vr + lane); vb1 = __ldg(vr + lane + 32);
    }
    float4* oa = (float4*)(out + (size_t)qa * SL);
    oa[lane] = va0; oa[lane + 32] = va1;
    if (has_b) {
        float4* ob = (float4*)(out + (size_t)qb * SL);
        ob[lane] = vb0; ob[lane + 32] = vb1;
    }
}

// ---------------------------------------------------------------------------
extern "C" void kernel_launch(void* const* d_in, const int* in_sizes, int n_in,
                              void* d_out, int out_size) {
    const float* syn = (const float*)d_in[0];   // [B, 256]
    const float* tk  = (const float*)d_in[1];   // [T, 256]
    const float* tv  = (const float*)d_in[2];   // [T, 256]
    float* out = (float*)d_out;                 // [B, 256]

    int B = in_sizes[0] / SL;
    int T = in_sizes[1] / SL;

    build_table_kernel<<<(T + 7) / 8, 256>>>(tk, T);
    // 8 warps/block, 2 queries/warp -> 16 queries per block.
    lookup_kernel<<<(B + 15) / 16, 256>>>(syn, tv, out, B);
}